// round 3
// baseline (speedup 1.0000x reference)
#include <cuda_runtime.h>
#include <math.h>

static constexpr int NIN   = 8192;   // inner dim for both layers
static constexpr int N_HID = 8192;
static constexpr int N_OUT = 1024;
static constexpr int STATS_BLOCKS = 32;                       // 32*256 = 8192 = one elem/thread
static constexpr int TOTAL_BLOCKS = STATS_BLOCKS + N_HID + N_OUT;  // 9248

#define FP_SCALE 268435456.0   // 2^28 fixed-point for deterministic atomic sum

// ---------------- scratch (no allocations allowed) ----------------
__device__ float g_z[NIN];         // layer-1 z = exp(x)
__device__ float g_hidden[N_HID];  // layer-1 output
__device__ float g_w2sum[N_OUT];   // W2 row sums

// all-zero-initializable accumulator block (single cudaMemsetAsync)
// [0] x-sum (fixed point)   [1] x maxpack (key<<32|idx)
// [2] x min as max(~key)    [3] stats-done counter
// [4] stats-ready flag      [5] global ticket
__device__ unsigned long long g_acc[6];

// order-preserving float<->uint key
__device__ __forceinline__ unsigned int fkey(float v) {
    unsigned u = __float_as_uint(v);
    return (u & 0x80000000u) ? ~u : (u | 0x80000000u);
}
__device__ __forceinline__ float fdec(unsigned int k) {
    unsigned u = (k & 0x80000000u) ? (k ^ 0x80000000u) : ~k;
    return __uint_as_float(u);
}

__global__ void __launch_bounds__(256) fused_kernel(const float* __restrict__ x,
                                                    const float* __restrict__ W1,
                                                    const float* __restrict__ W2,
                                                    float* __restrict__ out)
{
    const int bid = blockIdx.x;
    const int tid = threadIdx.x;
    const int wid = tid >> 5, lane = tid & 31;

    __shared__ float              shf[256];
    __shared__ int                shi[256];
    __shared__ unsigned long long sll[256];
    __shared__ float              swp[8];
    __shared__ int                s_mode;
    __shared__ float              s_tmp, s_Wsum;
    __shared__ int                s_last;

    volatile unsigned long long* va = (volatile unsigned long long*)g_acc;

    if (bid < STATS_BLOCKS) {
        // ================= x-stats blocks (first wave guaranteed) =============
        const int j = bid * 256 + tid;           // exactly one element per thread
        float v = expf(x[j]);
        g_z[j] = v;
        long long          lsum = __double2ll_rn((double)v * FP_SCALE);
        const unsigned     k    = fkey(v);
        unsigned           lmn  = ~k;            // min tracked as max of ~key
        unsigned long long lmx  = ((unsigned long long)k << 32) | (unsigned)j;

        sll[tid] = (unsigned long long)lsum; __syncthreads();
        for (int o = 128; o > 0; o >>= 1) { if (tid < o) sll[tid] = (unsigned long long)((long long)sll[tid] + (long long)sll[tid+o]); __syncthreads(); }
        const long long bsum = (long long)sll[0]; __syncthreads();

        unsigned* shu = (unsigned*)shi;
        shu[tid] = lmn; __syncthreads();
        for (int o = 128; o > 0; o >>= 1) { if (tid < o) shu[tid] = max(shu[tid], shu[tid+o]); __syncthreads(); }
        const unsigned bminneg = shu[0]; __syncthreads();

        sll[tid] = lmx; __syncthreads();
        for (int o = 128; o > 0; o >>= 1) { if (tid < o) sll[tid] = max(sll[tid], sll[tid+o]); __syncthreads(); }

        if (tid == 0) {
            atomicAdd(&g_acc[0], (unsigned long long)bsum);
            atomicMax(&g_acc[2], (unsigned long long)bminneg);
            atomicMax(&g_acc[1], sll[0]);
            __threadfence();
            if (atomicAdd(&g_acc[3], 1ULL) == (unsigned long long)(STATS_BLOCKS - 1))
                atomicExch(&g_acc[4], 1ULL);     // release stats
        }
    } else {
        // ================= row blocks: stream one W row =======================
        const bool  isW2 = (bid >= STATS_BLOCKS + N_HID);
        const float* __restrict__ W = isW2 ? W2 : W1;
        const int   row = isW2 ? (bid - STATS_BLOCKS - N_HID) : (bid - STATS_BLOCKS);
        const float4* __restrict__ Wr =
            reinterpret_cast<const float4*>(W + (size_t)row * NIN);

        float acc = 0.f;
        #pragma unroll
        for (int i = 0; i < NIN / 4 / 256; ++i) {
            float4 v = __ldcs(Wr + tid + i * 256);
            acc += (v.x + v.y) + (v.z + v.w);
        }
        #pragma unroll
        for (int o = 16; o > 0; o >>= 1) acc += __shfl_down_sync(0xffffffffu, acc, o);
        if (lane == 0) swp[wid] = acc;
        __syncthreads();

        if (isW2) {
            if (tid == 0) {
                float Wsum = 0.f;
                #pragma unroll
                for (int w = 0; w < 8; ++w) Wsum += swp[w];
                g_w2sum[row] = Wsum;
            }
        } else {
            // -------- layer-1 closed form --------
            if (tid == 0) {
                float Wsum = 0.f;
                #pragma unroll
                for (int w = 0; w < 8; ++w) Wsum += swp[w];

                while (va[4] == 0ULL) __nanosleep(64);   // wait for x-stats (rarely spins)
                __threadfence();                          // acquire

                const float Zsum = (float)((double)(long long)va[0] * (1.0 / FP_SCALE));
                const float zmin = fdec(~(unsigned)va[2]);
                const unsigned long long p = va[1];
                const float zmax = fdec((unsigned)(p >> 32));
                const int   jlast = (int)(unsigned)p;

                const float tmp = Wsum * Zsum / (Wsum - 1.f);
                int mode = 0;
                float result = INFINITY;
                if (Wsum > 1.f) {
                    if (zmin <= tmp) {               // first mismatch at i=0 -> k = n-1
                        float Wc = Wsum - W[(size_t)row * NIN + jlast];
                        float Zc = Zsum - zmax;
                        result = Wc * Zc / (Wc - 1.f);
                    }                                // else: no mismatch -> inf
                } else {
                    mode = 2; s_tmp = tmp; s_Wsum = Wsum;
                }
                s_mode = mode;
                if (mode == 0) g_hidden[row] = result;
            }
            __syncthreads();

            if (s_mode == 2) {
                // ---- rare general path (Wsum <= 1): cooperative pass ----
                if (tid == 0) __threadfence();   // acquire for g_z
                __syncthreads();
                const float tmp = s_tmp;
                int   cnt = 0;
                float sle = 0.f, wle = 0.f, m = -INFINITY;
                int   jm = -1;
                for (int j = tid; j < NIN; j += 256) {
                    float zj = g_z[j];
                    if (zj <= tmp) {
                        cnt++; sle += zj; wle += W[(size_t)row * NIN + j];
                        if (zj > m || (zj == m && j > jm)) { m = zj; jm = j; }
                    }
                }
                shi[tid] = cnt; __syncthreads();
                for (int o = 128; o > 0; o >>= 1) { if (tid < o) shi[tid] += shi[tid+o]; __syncthreads(); }
                const int c = shi[0]; __syncthreads();

                shf[tid] = sle; __syncthreads();
                for (int o = 128; o > 0; o >>= 1) { if (tid < o) shf[tid] += shf[tid+o]; __syncthreads(); }
                const float S_le = shf[0]; __syncthreads();

                shf[tid] = wle; __syncthreads();
                for (int o = 128; o > 0; o >>= 1) { if (tid < o) shf[tid] += shf[tid+o]; __syncthreads(); }
                const float W_le = shf[0]; __syncthreads();

                shf[tid] = m; shi[tid] = jm; __syncthreads();
                for (int o = 128; o > 0; o >>= 1) {
                    if (tid < o) {
                        float v2 = shf[tid+o]; int i2 = shi[tid+o];
                        if (v2 > shf[tid] || (v2 == shf[tid] && i2 > shi[tid])) { shf[tid] = v2; shi[tid] = i2; }
                    }
                    __syncthreads();
                }
                if (tid == 0) {
                    const float Zsum = (float)((double)(long long)va[0] * (1.0 / FP_SCALE));
                    const unsigned long long p = va[1];
                    const float zmax = fdec((unsigned)(p >> 32));
                    const int   jlast = (int)(unsigned)p;
                    const float Wsum = s_Wsum;
                    float result = INFINITY;
                    if (c == NIN) {
                    } else if (c == 0) {
                        float Wc = Wsum - W[(size_t)row * NIN + jlast];
                        float Zc = Zsum - zmax;
                        result = Wc * Zc / (Wc - 1.f);
                    } else if (c - 1 != 0) {
                        float Zc = S_le - shf[0];
                        float Wc = W_le - W[(size_t)row * NIN + shi[0]];
                        result = Wc * Zc / (Wc - 1.f);
                    }
                    g_hidden[row] = result;
                }
            }
        }
    }

    // ================= global ticket: last block runs layer-2 =================
    __syncthreads();
    if (tid == 0) {
        __threadfence();   // release this block's writes (g_hidden / g_w2sum)
        s_last = (atomicAdd(&g_acc[5], 1ULL) == (unsigned long long)(TOTAL_BLOCKS - 1)) ? 1 : 0;
        if (s_last) __threadfence();   // acquire everyone else's writes
    }
    __syncthreads();
    if (!s_last) return;

    // ---- hidden stats: fixed-order tree reduction (deterministic) ----
    float lsum = 0.f, lmn = INFINITY, lmx = -INFINITY;
    int   jm = -1;
    for (int j = tid; j < N_HID; j += 256) {
        float v = g_hidden[j];
        lsum += v;
        lmn = fminf(lmn, v);
        if (v > lmx || (v == lmx && j > jm)) { lmx = v; jm = j; }
    }
    shf[tid] = lsum; __syncthreads();
    for (int o = 128; o > 0; o >>= 1) { if (tid < o) shf[tid] += shf[tid+o]; __syncthreads(); }
    const float Zsum = shf[0]; __syncthreads();

    shf[tid] = lmn; __syncthreads();
    for (int o = 128; o > 0; o >>= 1) { if (tid < o) shf[tid] = fminf(shf[tid], shf[tid+o]); __syncthreads(); }
    const float zmin = shf[0]; __syncthreads();

    shf[tid] = lmx; shi[tid] = jm; __syncthreads();
    for (int o = 128; o > 0; o >>= 1) {
        if (tid < o) {
            float v2 = shf[tid+o]; int i2 = shi[tid+o];
            if (v2 > shf[tid] || (v2 == shf[tid] && i2 > shi[tid])) { shf[tid] = v2; shi[tid] = i2; }
        }
        __syncthreads();
    }
    const float zmax = shf[0];
    const int   jlast = shi[0];

    // ---- layer-2 closed form: 1024 rows, 4 per thread, independent loads ----
    #pragma unroll
    for (int r = tid; r < N_OUT; r += 256) {
        const float Wsum = g_w2sum[r];
        const float tmp = Wsum * Zsum / (Wsum - 1.f);
        float result = INFINITY;
        if (Wsum > 1.f) {
            if (zmin <= tmp) {
                float Wc = Wsum - W2[(size_t)r * NIN + jlast];
                float Zc = Zsum - zmax;
                result = Wc * Zc / (Wc - 1.f);
            }
        } else {
            // rare general path (never taken for this data): serial row scan
            int cnt = 0; float sle = 0.f, wle = 0.f, m = -INFINITY; int jmm = -1;
            for (int j = 0; j < NIN; ++j) {
                float zj = g_hidden[j];
                if (zj <= tmp) {
                    cnt++; sle += zj; wle += W2[(size_t)r * NIN + j];
                    if (zj > m || (zj == m && j > jmm)) { m = zj; jmm = j; }
                }
            }
            if (cnt == NIN) {
            } else if (cnt == 0) {
                float Wc = Wsum - W2[(size_t)r * NIN + jlast];
                float Zc = Zsum - zmax;
                result = Wc * Zc / (Wc - 1.f);
            } else if (cnt - 1 != 0) {
                float Zc = sle - m;
                float Wc = wle - W2[(size_t)r * NIN + jmm];
                result = Wc * Zc / (Wc - 1.f);
            }
        }
        out[r] = result;
    }
}

extern "C" void kernel_launch(void* const* d_in, const int* in_sizes, int n_in,
                              void* d_out, int out_size)
{
    const float* x  = (const float*)d_in[0];
    const float* W1 = (const float*)d_in[1];
    const float* W2 = (const float*)d_in[2];
    float* out = (float*)d_out;

    void* accp = nullptr;
    cudaGetSymbolAddress(&accp, g_acc);
    cudaMemsetAsync(accp, 0, sizeof(unsigned long long) * 6);

    fused_kernel<<<TOTAL_BLOCKS, 256>>>(x, W1, W2, out);
}

// round 4
// speedup vs baseline: 1.3436x; 1.3436x over previous
#include <cuda_runtime.h>
#include <math.h>

static constexpr int NIN   = 8192;   // inner dim for both layers
static constexpr int N_HID = 8192;
static constexpr int N_OUT = 1024;

// ---------------- scratch (no allocations allowed) ----------------
__device__ float g_z[NIN];         // layer-1 z = exp(x)
__device__ float g_hidden[N_HID];  // layer-1 output
__device__ float g_w2sum[N_OUT];   // W2 row sums

struct Stats { float Zsum, zmin, zmax; int jlast; };
__device__ Stats g_sx;   // stats of z
__device__ Stats g_sh;   // stats of hidden

// ---------------------------------------------------------------------------
// Single-block stats: deterministic fixed-order tree reduction.
// FIRST=true: also applies exp(x) and materializes g_z.
// ---------------------------------------------------------------------------
template<bool FIRST>
__global__ void __launch_bounds__(1024) stats_kernel(const float* __restrict__ x)
{
    const int tid = threadIdx.x;
    const float* __restrict__ src = FIRST ? x : g_hidden;

    float sum = 0.f, mn = INFINITY, mx = -INFINITY;
    int jm = -1;
    #pragma unroll
    for (int i = 0; i < NIN / 1024; ++i) {
        const int j = tid + i * 1024;
        float v = src[j];
        if (FIRST) { v = expf(v); g_z[j] = v; }
        sum += v;
        mn = fminf(mn, v);
        if (v > mx || (v == mx && j > jm)) { mx = v; jm = j; }
    }
    __shared__ float ss[1024], smn[1024], smx[1024];
    __shared__ int   sj[1024];
    ss[tid] = sum; smn[tid] = mn; smx[tid] = mx; sj[tid] = jm;
    __syncthreads();
    for (int o = 512; o > 0; o >>= 1) {
        if (tid < o) {
            ss[tid]  += ss[tid + o];
            smn[tid]  = fminf(smn[tid], smn[tid + o]);
            float v2 = smx[tid + o]; int i2 = sj[tid + o];
            if (v2 > smx[tid] || (v2 == smx[tid] && i2 > sj[tid])) { smx[tid] = v2; sj[tid] = i2; }
        }
        __syncthreads();
    }
    if (tid == 0) {
        Stats s; s.Zsum = ss[0]; s.zmin = smn[0]; s.zmax = smx[0]; s.jlast = sj[0];
        if (FIRST) g_sx = s; else g_sh = s;
    }
}

// ---------------------------------------------------------------------------
// The proven streaming wave (identical R2 inner loop): blocks [0,8192) do one
// W1 row each (layer-1 closed form -> g_hidden); blocks [8192,9216) do W2 row
// sums. Nothing synchronizing inside — stats arrive via kernel boundary.
// ---------------------------------------------------------------------------
__global__ void __launch_bounds__(256) big_kernel(const float* __restrict__ W1,
                                                  const float* __restrict__ W2)
{
    const int bid = blockIdx.x;
    const int tid = threadIdx.x;
    const bool isW2 = (bid >= N_HID);
    const float* __restrict__ W = isW2 ? W2 : W1;
    const int row = isW2 ? (bid - N_HID) : bid;
    const float4* __restrict__ Wr =
        reinterpret_cast<const float4*>(W + (size_t)row * NIN);

    float acc = 0.f;
    #pragma unroll
    for (int i = 0; i < NIN / 4 / 256; ++i) {
        float4 v = __ldcs(Wr + tid + i * 256);
        acc += (v.x + v.y) + (v.z + v.w);
    }
    #pragma unroll
    for (int o = 16; o > 0; o >>= 1) acc += __shfl_down_sync(0xffffffffu, acc, o);

    __shared__ float swp[8];
    const int wid = tid >> 5, lane = tid & 31;
    if (lane == 0) swp[wid] = acc;
    __syncthreads();

    if (isW2) {
        if (tid == 0) {
            float Wsum = 0.f;
            #pragma unroll
            for (int w = 0; w < 8; ++w) Wsum += swp[w];
            g_w2sum[row] = Wsum;
        }
        return;
    }

    // ---- layer-1 closed form ----
    __shared__ int   s_mode;
    __shared__ float s_tmp, s_Wsum;
    if (tid == 0) {
        float Wsum = 0.f;
        #pragma unroll
        for (int w = 0; w < 8; ++w) Wsum += swp[w];
        const float Zsum = g_sx.Zsum, zmin = g_sx.zmin, zmax = g_sx.zmax;
        const int   jlast = g_sx.jlast;
        const float tmp = Wsum * Zsum / (Wsum - 1.f);
        int mode = 0;
        float result = INFINITY;
        if (Wsum > 1.f) {
            if (zmin <= tmp) {                 // first mismatch at i=0 -> k = n-1
                float Wc = Wsum - W[(size_t)row * NIN + jlast];
                float Zc = Zsum - zmax;
                result = Wc * Zc / (Wc - 1.f);
            }                                  // else: no mismatch -> inf
        } else {
            mode = 2; s_tmp = tmp; s_Wsum = Wsum;
        }
        s_mode = mode;
        if (mode == 0) g_hidden[row] = result;
    }
    __syncthreads();
    if (s_mode != 2) return;

    // ---- rare general path (Wsum <= 1): cooperative pass over z and W row ----
    const float tmp = s_tmp;
    int   cnt = 0;
    float sle = 0.f, wle = 0.f, m = -INFINITY;
    int   jm = -1;
    for (int j = tid; j < NIN; j += 256) {
        float zj = g_z[j];
        if (zj <= tmp) {
            cnt++; sle += zj; wle += W[(size_t)row * NIN + j];
            if (zj > m || (zj == m && j > jm)) { m = zj; jm = j; }
        }
    }
    __shared__ float shf[256];
    __shared__ int   shi[256];

    shi[tid] = cnt; __syncthreads();
    for (int o = 128; o > 0; o >>= 1) { if (tid < o) shi[tid] += shi[tid + o]; __syncthreads(); }
    const int c = shi[0]; __syncthreads();

    shf[tid] = sle; __syncthreads();
    for (int o = 128; o > 0; o >>= 1) { if (tid < o) shf[tid] += shf[tid + o]; __syncthreads(); }
    const float S_le = shf[0]; __syncthreads();

    shf[tid] = wle; __syncthreads();
    for (int o = 128; o > 0; o >>= 1) { if (tid < o) shf[tid] += shf[tid + o]; __syncthreads(); }
    const float W_le = shf[0]; __syncthreads();

    shf[tid] = m; shi[tid] = jm; __syncthreads();
    for (int o = 128; o > 0; o >>= 1) {
        if (tid < o) {
            float v2 = shf[tid + o]; int i2 = shi[tid + o];
            if (v2 > shf[tid] || (v2 == shf[tid] && i2 > shi[tid])) { shf[tid] = v2; shi[tid] = i2; }
        }
        __syncthreads();
    }

    if (tid == 0) {
        const float Zsum = g_sx.Zsum, zmax = g_sx.zmax;
        const int   jlast = g_sx.jlast;
        const float Wsum = s_Wsum;
        float result = INFINITY;
        if (c == NIN) {
            // no mismatch -> inf
        } else if (c == 0) {
            float Wc = Wsum - W[(size_t)row * NIN + jlast];
            float Zc = Zsum - zmax;
            result = Wc * Zc / (Wc - 1.f);
        } else if (c - 1 != 0) {
            float Zc = S_le - shf[0];
            float Wc = W_le - W[(size_t)row * NIN + shi[0]];
            result = Wc * Zc / (Wc - 1.f);
        }
        g_hidden[row] = result;
    }
}

// ---------------------------------------------------------------------------
// Layer-2 epilogue: one thread per output row; one independent W2 gather each.
// ---------------------------------------------------------------------------
__global__ void __launch_bounds__(256) epilogue_kernel(const float* __restrict__ W2,
                                                       float* __restrict__ out)
{
    const int r = blockIdx.x * 256 + threadIdx.x;
    if (r >= N_OUT) return;

    const float Zsum = g_sh.Zsum, zmin = g_sh.zmin, zmax = g_sh.zmax;
    const int   jlast = g_sh.jlast;
    const float Wsum = g_w2sum[r];
    const float tmp = Wsum * Zsum / (Wsum - 1.f);
    float result = INFINITY;

    if (Wsum > 1.f) {
        if (zmin <= tmp) {
            float Wc = Wsum - W2[(size_t)r * NIN + jlast];
            float Zc = Zsum - zmax;
            result = Wc * Zc / (Wc - 1.f);
        }
    } else {
        // rare general path (never taken for this data): serial row scan
        int cnt = 0; float sle = 0.f, wle = 0.f, m = -INFINITY; int jm = -1;
        for (int j = 0; j < NIN; ++j) {
            float zj = g_hidden[j];
            if (zj <= tmp) {
                cnt++; sle += zj; wle += W2[(size_t)r * NIN + j];
                if (zj > m || (zj == m && j > jm)) { m = zj; jm = j; }
            }
        }
        if (cnt == NIN) {
            // inf
        } else if (cnt == 0) {
            float Wc = Wsum - W2[(size_t)r * NIN + jlast];
            float Zc = Zsum - zmax;
            result = Wc * Zc / (Wc - 1.f);
        } else if (cnt - 1 != 0) {
            float Zc = sle - m;
            float Wc = wle - W2[(size_t)r * NIN + jm];
            result = Wc * Zc / (Wc - 1.f);
        }
    }
    out[r] = result;
}

extern "C" void kernel_launch(void* const* d_in, const int* in_sizes, int n_in,
                              void* d_out, int out_size)
{
    const float* x  = (const float*)d_in[0];
    const float* W1 = (const float*)d_in[1];
    const float* W2 = (const float*)d_in[2];
    float* out = (float*)d_out;

    stats_kernel<true><<<1, 1024>>>(x);          // z = exp(x); stats of z
    big_kernel<<<N_HID + N_OUT, 256>>>(W1, W2);  // layer-1 + W2 row sums (288 MB stream)
    stats_kernel<false><<<1, 1024>>>(nullptr);   // stats of hidden
    epilogue_kernel<<<(N_OUT + 255) / 256, 256>>>(W2, out);  // layer-2 closed form
}

// round 5
// speedup vs baseline: 1.3937x; 1.0373x over previous
#include <cuda_runtime.h>
#include <math.h>

static constexpr int NIN   = 8192;   // inner dim for both layers
static constexpr int N_HID = 8192;
static constexpr int N_OUT = 1024;

// ---------------- scratch (no allocations allowed) ----------------
__device__ float g_z[NIN];         // layer-1 z = exp(x)
__device__ float g_hidden[N_HID];  // layer-1 output
__device__ float g_w2sum[N_OUT];   // W2 row sums

struct Stats { float Zsum, zmin, zmax; int jlast; };
__device__ Stats g_sx;   // stats of z

// ---------------------------------------------------------------------------
// Stats over z = exp(x): single block, deterministic fixed-order tree.
// ---------------------------------------------------------------------------
__global__ void __launch_bounds__(1024) statsx_kernel(const float* __restrict__ x)
{
    const int tid = threadIdx.x;
    float sum = 0.f, mn = INFINITY, mx = -INFINITY;
    int jm = -1;
    #pragma unroll
    for (int i = 0; i < NIN / 1024; ++i) {
        const int j = tid + i * 1024;
        float v = expf(x[j]);
        g_z[j] = v;
        sum += v;
        mn = fminf(mn, v);
        if (v > mx || (v == mx && j > jm)) { mx = v; jm = j; }
    }
    __shared__ float ss[1024], smn[1024], smx[1024];
    __shared__ int   sj[1024];
    ss[tid] = sum; smn[tid] = mn; smx[tid] = mx; sj[tid] = jm;
    __syncthreads();
    for (int o = 512; o > 0; o >>= 1) {
        if (tid < o) {
            ss[tid]  += ss[tid + o];
            smn[tid]  = fminf(smn[tid], smn[tid + o]);
            float v2 = smx[tid + o]; int i2 = sj[tid + o];
            if (v2 > smx[tid] || (v2 == smx[tid] && i2 > sj[tid])) { smx[tid] = v2; sj[tid] = i2; }
        }
        __syncthreads();
    }
    if (tid == 0) {
        Stats s; s.Zsum = ss[0]; s.zmin = smn[0]; s.zmax = smx[0]; s.jlast = sj[0];
        g_sx = s;
    }
}

// ---------------------------------------------------------------------------
// The proven streaming wave (identical R2/R4 inner loop): blocks [0,8192) do
// one W1 row each (layer-1 closed form -> g_hidden); blocks [8192,9216) do W2
// row sums. Nothing synchronizing inside.
// ---------------------------------------------------------------------------
__global__ void __launch_bounds__(256) big_kernel(const float* __restrict__ W1,
                                                  const float* __restrict__ W2)
{
    const int bid = blockIdx.x;
    const int tid = threadIdx.x;
    const bool isW2 = (bid >= N_HID);
    const float* __restrict__ W = isW2 ? W2 : W1;
    const int row = isW2 ? (bid - N_HID) : bid;
    const float4* __restrict__ Wr =
        reinterpret_cast<const float4*>(W + (size_t)row * NIN);

    float acc = 0.f;
    #pragma unroll
    for (int i = 0; i < NIN / 4 / 256; ++i) {
        float4 v = __ldcs(Wr + tid + i * 256);
        acc += (v.x + v.y) + (v.z + v.w);
    }
    #pragma unroll
    for (int o = 16; o > 0; o >>= 1) acc += __shfl_down_sync(0xffffffffu, acc, o);

    __shared__ float swp[8];
    const int wid = tid >> 5, lane = tid & 31;
    if (lane == 0) swp[wid] = acc;
    __syncthreads();

    if (isW2) {
        if (tid == 0) {
            float Wsum = 0.f;
            #pragma unroll
            for (int w = 0; w < 8; ++w) Wsum += swp[w];
            g_w2sum[row] = Wsum;
        }
        return;
    }

    // ---- layer-1 closed form ----
    __shared__ int   s_mode;
    __shared__ float s_tmp, s_Wsum;
    if (tid == 0) {
        float Wsum = 0.f;
        #pragma unroll
        for (int w = 0; w < 8; ++w) Wsum += swp[w];
        const float Zsum = g_sx.Zsum, zmin = g_sx.zmin, zmax = g_sx.zmax;
        const int   jlast = g_sx.jlast;
        const float tmp = Wsum * Zsum / (Wsum - 1.f);
        int mode = 0;
        float result = INFINITY;
        if (Wsum > 1.f) {
            if (zmin <= tmp) {                 // first mismatch at i=0 -> k = n-1
                float Wc = Wsum - W[(size_t)row * NIN + jlast];
                float Zc = Zsum - zmax;
                result = Wc * Zc / (Wc - 1.f);
            }                                  // else: no mismatch -> inf
        } else {
            mode = 2; s_tmp = tmp; s_Wsum = Wsum;
        }
        s_mode = mode;
        if (mode == 0) g_hidden[row] = result;
    }
    __syncthreads();
    if (s_mode != 2) return;

    // ---- rare general path (Wsum <= 1): cooperative pass over z and W row ----
    const float tmp = s_tmp;
    int   cnt = 0;
    float sle = 0.f, wle = 0.f, m = -INFINITY;
    int   jm = -1;
    for (int j = tid; j < NIN; j += 256) {
        float zj = g_z[j];
        if (zj <= tmp) {
            cnt++; sle += zj; wle += W[(size_t)row * NIN + j];
            if (zj > m || (zj == m && j > jm)) { m = zj; jm = j; }
        }
    }
    __shared__ float shf[256];
    __shared__ int   shi[256];

    shi[tid] = cnt; __syncthreads();
    for (int o = 128; o > 0; o >>= 1) { if (tid < o) shi[tid] += shi[tid + o]; __syncthreads(); }
    const int c = shi[0]; __syncthreads();

    shf[tid] = sle; __syncthreads();
    for (int o = 128; o > 0; o >>= 1) { if (tid < o) shf[tid] += shf[tid + o]; __syncthreads(); }
    const float S_le = shf[0]; __syncthreads();

    shf[tid] = wle; __syncthreads();
    for (int o = 128; o > 0; o >>= 1) { if (tid < o) shf[tid] += shf[tid + o]; __syncthreads(); }
    const float W_le = shf[0]; __syncthreads();

    shf[tid] = m; shi[tid] = jm; __syncthreads();
    for (int o = 128; o > 0; o >>= 1) {
        if (tid < o) {
            float v2 = shf[tid + o]; int i2 = shi[tid + o];
            if (v2 > shf[tid] || (v2 == shf[tid] && i2 > shi[tid])) { shf[tid] = v2; shi[tid] = i2; }
        }
        __syncthreads();
    }

    if (tid == 0) {
        const float Zsum = g_sx.Zsum, zmax = g_sx.zmax;
        const int   jlast = g_sx.jlast;
        const float Wsum = s_Wsum;
        float result = INFINITY;
        if (c == NIN) {
            // no mismatch -> inf
        } else if (c == 0) {
            float Wc = Wsum - W[(size_t)row * NIN + jlast];
            float Zc = Zsum - zmax;
            result = Wc * Zc / (Wc - 1.f);
        } else if (c - 1 != 0) {
            float Zc = S_le - shf[0];
            float Wc = W_le - W[(size_t)row * NIN + shi[0]];
            result = Wc * Zc / (Wc - 1.f);
        }
        g_hidden[row] = result;
    }
}

// ---------------------------------------------------------------------------
// Fused finale: ONE block of 1024 threads.
//   phase 1: stats over g_hidden (deterministic fixed-order tree)
//   phase 2: layer-2 closed form, one output row per thread
// Replaces the former statsh launch + grid-4 epilogue launch + boundary.
// ---------------------------------------------------------------------------
__global__ void __launch_bounds__(1024) finale_kernel(const float* __restrict__ W2,
                                                      float* __restrict__ out)
{
    const int tid = threadIdx.x;

    // ---- phase 1: hidden stats ----
    float sum = 0.f, mn = INFINITY, mx = -INFINITY;
    int jm = -1;
    #pragma unroll
    for (int i = 0; i < N_HID / 1024; ++i) {
        const int j = tid + i * 1024;
        float v = g_hidden[j];
        sum += v;
        mn = fminf(mn, v);
        if (v > mx || (v == mx && j > jm)) { mx = v; jm = j; }
    }
    __shared__ float ss[1024], smn[1024], smx[1024];
    __shared__ int   sj[1024];
    ss[tid] = sum; smn[tid] = mn; smx[tid] = mx; sj[tid] = jm;
    __syncthreads();
    for (int o = 512; o > 0; o >>= 1) {
        if (tid < o) {
            ss[tid]  += ss[tid + o];
            smn[tid]  = fminf(smn[tid], smn[tid + o]);
            float v2 = smx[tid + o]; int i2 = sj[tid + o];
            if (v2 > smx[tid] || (v2 == smx[tid] && i2 > sj[tid])) { smx[tid] = v2; sj[tid] = i2; }
        }
        __syncthreads();
    }
    const float Zsum = ss[0];
    const float zmin = smn[0];
    const float zmax = smx[0];
    const int   jlast = sj[0];
    __syncthreads();

    // ---- phase 2: layer-2 closed form, one row per thread ----
    const int r = tid;
    if (r >= N_OUT) return;

    const float Wsum = g_w2sum[r];
    const float tmp = Wsum * Zsum / (Wsum - 1.f);
    float result = INFINITY;

    if (Wsum > 1.f) {
        if (zmin <= tmp) {
            float Wc = Wsum - W2[(size_t)r * NIN + jlast];
            float Zc = Zsum - zmax;
            result = Wc * Zc / (Wc - 1.f);
        }
    } else {
        // rare general path (never taken for this data): serial row scan
        int cnt = 0; float sle = 0.f, wle = 0.f, m = -INFINITY; int jmm = -1;
        for (int j = 0; j < NIN; ++j) {
            float zj = g_hidden[j];
            if (zj <= tmp) {
                cnt++; sle += zj; wle += W2[(size_t)r * NIN + j];
                if (zj > m || (zj == m && j > jmm)) { m = zj; jmm = j; }
            }
        }
        if (cnt == NIN) {
            // inf
        } else if (cnt == 0) {
            float Wc = Wsum - W2[(size_t)r * NIN + jlast];
            float Zc = Zsum - zmax;
            result = Wc * Zc / (Wc - 1.f);
        } else if (cnt - 1 != 0) {
            float Zc = sle - m;
            float Wc = wle - W2[(size_t)r * NIN + jmm];
            result = Wc * Zc / (Wc - 1.f);
        }
    }
    out[r] = result;
}

extern "C" void kernel_launch(void* const* d_in, const int* in_sizes, int n_in,
                              void* d_out, int out_size)
{
    const float* x  = (const float*)d_in[0];
    const float* W1 = (const float*)d_in[1];
    const float* W2 = (const float*)d_in[2];
    float* out = (float*)d_out;

    statsx_kernel<<<1, 1024>>>(x);               // z = exp(x); stats of z
    big_kernel<<<N_HID + N_OUT, 256>>>(W1, W2);  // layer-1 + W2 row sums (288 MB)
    finale_kernel<<<1, 1024>>>(W2, out);         // hidden stats + layer-2
}